// round 14
// baseline (speedup 1.0000x reference)
#include <cuda_runtime.h>
#include <cuda_bf16.h>

// NeuralNetwork ODE scan: B=8192 trajectories, N=2048 steps, 5->10(tanh)->5 MLP.
// R13 vs R11 (291us, issue=16.8%): each thread now advances TWO independent
// trajectories (traj, traj+B/2), interleaved. If the unexplained ~150 cyc/step
// residual is latency bubbles, the second chain fills them (~free); if it's a
// throughput term, duration stays flat -- decisive either way.
// Also: __launch_bounds__(128,1) lifts the 64-reg cap; tree-reduced sc/sr.
// Retained from R11: 2-lane split (shfl_xor 1), register-batched double-buffered
// t loads (8-step blocks), tanh.approx, branchless paired stores, zb pipeline.

__device__ __forceinline__ float fast_tanh(float z) {
    float r;
    asm("tanh.approx.f32 %0, %1;" : "=f"(r) : "f"(z));
    return r;
}

// partial MLP for one trajectory: a[u]=tanh(zb[u]+yc*w1c[u]+yr*w1r[u]);
// sc/sr = tree-reduced partial output dots (cols 3,4).
__device__ __forceinline__ void mlp_partial(
    float yc, float yr, const float (&zb)[5],
    const float (&w1c)[5], const float (&w1r)[5],
    const float (&w2c)[5], const float (&w2r)[5],
    float scInit, float srInit, float& sc, float& sr)
{
    float a[5];
#pragma unroll
    for (int u = 0; u < 5; ++u) {
        float z = fmaf(yr, w1r[u], fmaf(yc, w1c[u], zb[u]));
        a[u] = fast_tanh(z);
    }
    // tree reduction (depth ~3 vs serial 5)
    float c0 = fmaf(a[1], w2c[1], a[0] * w2c[0]);
    float c1 = fmaf(a[3], w2c[3], a[2] * w2c[2]);
    float c2 = fmaf(a[4], w2c[4], scInit);
    sc = (c0 + c1) + c2;
    float r0 = fmaf(a[1], w2r[1], a[0] * w2r[0]);
    float r1 = fmaf(a[3], w2r[3], a[2] * w2r[2]);
    float r2 = fmaf(a[4], w2r[4], srInit);
    sr = (r0 + r1) + r2;
}

__global__ void __launch_bounds__(128, 1)
ode_scan_kernel(const float* __restrict__ t,
                const float* __restrict__ Vsto,
                const float* __restrict__ Temp,
                const float* __restrict__ Cap0,
                const float* __restrict__ Res0,
                const float* __restrict__ W1,   // (5,10) row-major
                const float* __restrict__ b1,   // (10)
                const float* __restrict__ W2,   // (10,5) row-major
                const float* __restrict__ b2,   // (5)
                float* __restrict__ out,        // (B, Np1, 2)
                int B, int Np1)
{
    int gtid = blockIdx.x * blockDim.x + threadIdx.x;
    int pair = gtid >> 1;
    int half = gtid & 1;          // which 5 hidden units this lane owns
    const int halfB = B >> 1;
    if (pair >= halfB) return;

    const int trajA = pair;
    const int trajB = pair + halfB;
    const int j0 = half * 5;

    // shared weight registers (identical for both trajectories)
    float w1t[5], w1c[5], w1r[5], w2c[5], w2r[5];
    float cjA[5], cjB[5];
    const float y1A = Vsto[trajA], y2A = Temp[trajA];
    const float y1B = Vsto[trajB], y2B = Temp[trajB];
#pragma unroll
    for (int u = 0; u < 5; ++u) {
        int j = j0 + u;
        w1t[u] = W1[0 * 10 + j];
        w1c[u] = W1[3 * 10 + j];
        w1r[u] = W1[4 * 10 + j];
        float b = b1[j];
        cjA[u] = fmaf(y2A, W1[2 * 10 + j], fmaf(y1A, W1[1 * 10 + j], b));
        cjB[u] = fmaf(y2B, W1[2 * 10 + j], fmaf(y1B, W1[1 * 10 + j], b));
        w2c[u] = W2[j * 5 + 3];
        w2r[u] = W2[j * 5 + 4];
    }
    const float scInit = (half == 0) ? b2[3] : 0.0f;
    const float srInit = (half == 0) ? b2[4] : 0.0f;

    float ycA = Cap0[trajA], yrA = Res0[trajA];
    float ycB = Cap0[trajB], yrB = Res0[trajB];

    const float* trowA = t + (size_t)trajA * (size_t)Np1;
    const float* trowB = t + (size_t)trajB * (size_t)Np1;
    float* orowA = out + 2 * (size_t)trajA * (size_t)Np1;
    float* orowB = out + 2 * (size_t)trajB * (size_t)Np1;

    orowA[half] = half ? yrA : ycA;
    orowB[half] = half ? yrB : ycB;

    const int last = Np1 - 1;
    float tprevA = trowA[0], tcurA = trowA[1];
    float tprevB = trowB[0], tcurB = trowB[1];

    float zbA[5], zbB[5];
#pragma unroll
    for (int u = 0; u < 5; ++u) {
        zbA[u] = fmaf(tprevA, w1t[u], cjA[u]);
        zbB[u] = fmaf(tprevB, w1t[u], cjB[u]);
    }

    // double-buffered t blocks: tb*[k] = tnext for step i = ib + k
    float tbA[8], tnbA[8], tbB[8], tnbB[8];
#pragma unroll
    for (int k = 0; k < 8; ++k) {
        int idx = 2 + k; idx = (idx <= last) ? idx : last;
        tbA[k] = trowA[idx];
        tbB[k] = trowB[idx];
    }

    int ib = 1;
    while (ib + 8 <= last) {
        // issue next block's independent loads NOW (consumed >=8 steps later)
#pragma unroll
        for (int k = 0; k < 8; ++k) {
            int idx = ib + 9 + k; idx = (idx <= last) ? idx : last;
            tnbA[k] = trowA[idx];
            tnbB[k] = trowB[idx];
        }
#pragma unroll
        for (int k = 0; k < 8; ++k) {
            const int i = ib + k;
            const float hA = tcurA - tprevA;
            const float hB = tcurB - tprevB;

            float scA, srA, scB, srB;
            mlp_partial(ycA, yrA, zbA, w1c, w1r, w2c, w2r, scInit, srInit, scA, srA);
            mlp_partial(ycB, yrB, zbB, w1c, w1r, w2c, w2r, scInit, srInit, scB, srB);

            // next zb depends only on tcur — overlaps the shfls below
#pragma unroll
            for (int u = 0; u < 5; ++u) {
                zbA[u] = fmaf(tcurA, w1t[u], cjA[u]);
                zbB[u] = fmaf(tcurB, w1t[u], cjB[u]);
            }

            // 4 independent shfls, back-to-back (latencies overlap)
            scA += __shfl_xor_sync(0xFFFFFFFFu, scA, 1);
            srA += __shfl_xor_sync(0xFFFFFFFFu, srA, 1);
            scB += __shfl_xor_sync(0xFFFFFFFFu, scB, 1);
            srB += __shfl_xor_sync(0xFFFFFFFFu, srB, 1);

            ycA = fmaf(hA, scA, ycA);
            yrA = fmaf(hA, srA, yrA);
            ycB = fmaf(hB, scB, ycB);
            yrB = fmaf(hB, srB, yrB);

            orowA[2 * i + half] = half ? yrA : ycA;
            orowB[2 * i + half] = half ? yrB : ycB;

            tprevA = tcurA; tcurA = tbA[k];
            tprevB = tcurB; tcurB = tbB[k];
        }
#pragma unroll
        for (int k = 0; k < 8; ++k) { tbA[k] = tnbA[k]; tbB[k] = tnbB[k]; }
        ib += 8;
    }

    // scalar tail + final step: i = ib .. last
    for (int i = ib; i <= last; ++i) {
        const float tnA = (i < last) ? trowA[i + 1] : tcurA;
        const float tnB = (i < last) ? trowB[i + 1] : tcurB;
        const float hA = tcurA - tprevA;
        const float hB = tcurB - tprevB;

        float scA, srA, scB, srB;
        mlp_partial(ycA, yrA, zbA, w1c, w1r, w2c, w2r, scInit, srInit, scA, srA);
        mlp_partial(ycB, yrB, zbB, w1c, w1r, w2c, w2r, scInit, srInit, scB, srB);

#pragma unroll
        for (int u = 0; u < 5; ++u) {
            zbA[u] = fmaf(tcurA, w1t[u], cjA[u]);
            zbB[u] = fmaf(tcurB, w1t[u], cjB[u]);
        }

        scA += __shfl_xor_sync(0xFFFFFFFFu, scA, 1);
        srA += __shfl_xor_sync(0xFFFFFFFFu, srA, 1);
        scB += __shfl_xor_sync(0xFFFFFFFFu, scB, 1);
        srB += __shfl_xor_sync(0xFFFFFFFFu, srB, 1);

        ycA = fmaf(hA, scA, ycA);
        yrA = fmaf(hA, srA, yrA);
        ycB = fmaf(hB, scB, ycB);
        yrB = fmaf(hB, srB, yrB);

        orowA[2 * i + half] = half ? yrA : ycA;
        orowB[2 * i + half] = half ? yrB : ycB;

        tprevA = tcurA; tcurA = tnA;
        tprevB = tcurB; tcurB = tnB;
    }
}

extern "C" void kernel_launch(void* const* d_in, const int* in_sizes, int n_in,
                              void* d_out, int out_size) {
    const float* t    = (const float*)d_in[0];
    const float* V    = (const float*)d_in[1];
    const float* Temp = (const float*)d_in[2];
    const float* Cap0 = (const float*)d_in[3];
    const float* Res0 = (const float*)d_in[4];
    const float* W1   = (const float*)d_in[5];
    const float* b1   = (const float*)d_in[6];
    const float* W2   = (const float*)d_in[7];
    const float* b2   = (const float*)d_in[8];
    float* out = (float*)d_out;

    const int B   = in_sizes[1];              // V_sto has B elements
    const int Np1 = in_sizes[0] / B;          // t is (B, N+1)

    const int threads = B;                    // 2 lanes/pair, 2 trajs/thread
    const int block = 128;
    const int grid = (threads + block - 1) / block;
    ode_scan_kernel<<<grid, block>>>(t, V, Temp, Cap0, Res0, W1, b1, W2, b2,
                                     out, B, Np1);
}

// round 15
// speedup vs baseline: 2.0520x; 2.0520x over previous
#include <cuda_runtime.h>
#include <cuda_bf16.h>

// NeuralNetwork ODE scan: B=8192 trajectories, N=2048 steps, 5->10(tanh)->5 MLP.
// R14 vs R11 (291us) / R13 (433us, proved chain interleaving works but halved
// the grid): 4 lanes per trajectory (butterfly xor1+xor2), 3 hidden units per
// lane (padded 10->12 with zero weights). 32768 threads = 1024 warps, launched
// block=256 grid=128 -> exactly 2 warps per SMSP on 128 SMs; the SMSP arbiter
// interleaves two independent chains (cross-warp bubble filling, zero register
// cost). Retained: register-batched double-buffered t loads, tanh.approx,
// zb pipeline, predicated single-STG stores.

__device__ __forceinline__ float fast_tanh(float z) {
    float r;
    asm("tanh.approx.f32 %0, %1;" : "=f"(r) : "f"(z));
    return r;
}

__global__ void __launch_bounds__(256, 1)
ode_scan_kernel(const float* __restrict__ t,
                const float* __restrict__ Vsto,
                const float* __restrict__ Temp,
                const float* __restrict__ Cap0,
                const float* __restrict__ Res0,
                const float* __restrict__ W1,   // (5,10) row-major
                const float* __restrict__ b1,   // (10)
                const float* __restrict__ W2,   // (10,5) row-major
                const float* __restrict__ b2,   // (5)
                float* __restrict__ out,        // (B, Np1, 2)
                int B, int Np1)
{
    int gtid = blockIdx.x * blockDim.x + threadIdx.x;
    int traj = gtid >> 2;
    int q    = gtid & 3;          // lane quarter: owns hidden units q*3..q*3+2 (j<10)
    if (traj >= B) return;

    // Per-lane weight registers, zero-padded for j >= 10
    float w1t[3], w1c[3], w1r[3], cj[3], w2c[3], w2r[3];
    const float y1 = Vsto[traj];
    const float y2 = Temp[traj];
#pragma unroll
    for (int u = 0; u < 3; ++u) {
        int j = q * 3 + u;
        bool valid = (j < 10);
        int jj = valid ? j : 0;
        float m = valid ? 1.0f : 0.0f;
        w1t[u] = m * W1[0 * 10 + jj];
        w1c[u] = m * W1[3 * 10 + jj];
        w1r[u] = m * W1[4 * 10 + jj];
        cj[u]  = m * fmaf(y2, W1[2 * 10 + jj], fmaf(y1, W1[1 * 10 + jj], b1[jj]));
        w2c[u] = m * W2[jj * 5 + 3];
        w2r[u] = m * W2[jj * 5 + 4];
    }
    // b2 folded into lane-quarter 0's partial sums
    const float scInit = (q == 0) ? b2[3] : 0.0f;
    const float srInit = (q == 0) ? b2[4] : 0.0f;

    float yc = Cap0[traj];
    float yr = Res0[traj];

    const float* trow = t + (size_t)traj * (size_t)Np1;
    float* orow = out + 2 * (size_t)traj * (size_t)Np1;

    // initial state: quarters 0,1 store yc,yr (single predicated STG)
    if (q < 2) orow[q] = q ? yr : yc;

    const int last = Np1 - 1;
    float tprev = trow[0];
    float tcur  = trow[1];

    // zb[u] = cj[u] + tprev*w1t[u]  (part of z independent of yc/yr)
    float zb[3];
#pragma unroll
    for (int u = 0; u < 3; ++u) zb[u] = fmaf(tprev, w1t[u], cj[u]);

    // tb[k] = tnext for step i = ib + k; double-buffered blocks of 8
    float tb[8], tnb[8];
#pragma unroll
    for (int k = 0; k < 8; ++k) {
        int idx = 2 + k; idx = (idx <= last) ? idx : last;
        tb[k] = trow[idx];
    }

    int ib = 1;
    while (ib + 8 <= last) {
        // issue next block's 8 independent loads NOW (consumed >=8 steps later)
#pragma unroll
        for (int k = 0; k < 8; ++k) {
            int idx = ib + 9 + k; idx = (idx <= last) ? idx : last;
            tnb[k] = trow[idx];
        }
#pragma unroll
        for (int k = 0; k < 8; ++k) {
            const int i = ib + k;
            const float h = tcur - tprev;

            float a0, a1, a2;
            {
                float z0 = fmaf(yr, w1r[0], fmaf(yc, w1c[0], zb[0]));
                float z1 = fmaf(yr, w1r[1], fmaf(yc, w1c[1], zb[1]));
                float z2 = fmaf(yr, w1r[2], fmaf(yc, w1c[2], zb[2]));
                a0 = fast_tanh(z0); a1 = fast_tanh(z1); a2 = fast_tanh(z2);
            }
            float sc = fmaf(a2, w2c[2], fmaf(a1, w2c[1], fmaf(a0, w2c[0], scInit)));
            float sr = fmaf(a2, w2r[2], fmaf(a1, w2r[1], fmaf(a0, w2r[0], srInit)));

            // next zb depends only on tcur — overlaps the butterfly below
#pragma unroll
            for (int u = 0; u < 3; ++u) zb[u] = fmaf(tcur, w1t[u], cj[u]);

            // 2-stage butterfly over the 4 lane-quarters
            sc += __shfl_xor_sync(0xFFFFFFFFu, sc, 1);
            sr += __shfl_xor_sync(0xFFFFFFFFu, sr, 1);
            sc += __shfl_xor_sync(0xFFFFFFFFu, sc, 2);
            sr += __shfl_xor_sync(0xFFFFFFFFu, sr, 2);

            yc = fmaf(h, sc, yc);
            yr = fmaf(h, sr, yr);

            if (q < 2) orow[2 * i + q] = q ? yr : yc;

            tprev = tcur;
            tcur = tb[k];
        }
#pragma unroll
        for (int k = 0; k < 8; ++k) tb[k] = tnb[k];
        ib += 8;
    }

    // tail + final step: i = ib .. last
    for (int i = ib; i <= last; ++i) {
        const float tnext = (i < last) ? trow[i + 1] : tcur;
        const float h = tcur - tprev;

        float z0 = fmaf(yr, w1r[0], fmaf(yc, w1c[0], zb[0]));
        float z1 = fmaf(yr, w1r[1], fmaf(yc, w1c[1], zb[1]));
        float z2 = fmaf(yr, w1r[2], fmaf(yc, w1c[2], zb[2]));
        float a0 = fast_tanh(z0), a1 = fast_tanh(z1), a2 = fast_tanh(z2);

        float sc = fmaf(a2, w2c[2], fmaf(a1, w2c[1], fmaf(a0, w2c[0], scInit)));
        float sr = fmaf(a2, w2r[2], fmaf(a1, w2r[1], fmaf(a0, w2r[0], srInit)));

#pragma unroll
        for (int u = 0; u < 3; ++u) zb[u] = fmaf(tcur, w1t[u], cj[u]);

        sc += __shfl_xor_sync(0xFFFFFFFFu, sc, 1);
        sr += __shfl_xor_sync(0xFFFFFFFFu, sr, 1);
        sc += __shfl_xor_sync(0xFFFFFFFFu, sc, 2);
        sr += __shfl_xor_sync(0xFFFFFFFFu, sr, 2);

        yc = fmaf(h, sc, yc);
        yr = fmaf(h, sr, yr);

        if (q < 2) orow[2 * i + q] = q ? yr : yc;

        tprev = tcur;
        tcur = tnext;
    }
}

extern "C" void kernel_launch(void* const* d_in, const int* in_sizes, int n_in,
                              void* d_out, int out_size) {
    const float* t    = (const float*)d_in[0];
    const float* V    = (const float*)d_in[1];
    const float* Temp = (const float*)d_in[2];
    const float* Cap0 = (const float*)d_in[3];
    const float* Res0 = (const float*)d_in[4];
    const float* W1   = (const float*)d_in[5];
    const float* b1   = (const float*)d_in[6];
    const float* W2   = (const float*)d_in[7];
    const float* b2   = (const float*)d_in[8];
    float* out = (float*)d_out;

    const int B   = in_sizes[1];              // V_sto has B elements
    const int Np1 = in_sizes[0] / B;          // t is (B, N+1)

    const int threads = 4 * B;                // 4 lanes per trajectory
    const int block = 256;                    // 8 warps/block -> 2 warps/SMSP
    const int grid = (threads + block - 1) / block;
    ode_scan_kernel<<<grid, block>>>(t, V, Temp, Cap0, Res0, W1, b1, W2, b2,
                                     out, B, Np1);
}